// round 1
// baseline (speedup 1.0000x reference)
#include <cuda_runtime.h>
#include <math.h>

#define G    128      // B*T graphs
#define NN   1000
#define FIN  16
#define HH   4
#define DD   32
#define HD   128
#define EE   16000
#define EA   17000    // + self loops
#define HL   64
#define TT   16
#define BB   8
#define NOUT 8

#define FULL 0xffffffffu

// ---- scratch (device globals; no allocations allowed) ----
__device__ float g_xp[G * NN * HD];     // 65.5 MB, mostly L2-resident
__device__ float g_as[G * NN * HH];
__device__ float g_ad[G * NN * HH];
__device__ float g_pooled[G * HD];
__device__ int   g_deg[NN];
__device__ int   g_off[NN + 1];
__device__ int   g_cursor[NN];
__device__ int   g_csr[EA];

// ---------------- CSR build ----------------
__global__ void k_zero() {
    int i = blockIdx.x * blockDim.x + threadIdx.x;
    if (i < NN) { g_deg[i] = 0; g_cursor[i] = 0; }
    if (i < G * HD) g_pooled[i] = 0.0f;   // relu output >= 0, so 0 is a safe max-identity
}

__global__ void k_count(const int* __restrict__ ei) {
    int i = blockIdx.x * blockDim.x + threadIdx.x;
    if (i >= EA) return;
    int d = (i < EE) ? ei[EE + i] : (i - EE);   // ei: [2,E] row-major; row1 = dst
    atomicAdd(&g_deg[d], 1);
}

__global__ void k_scan() {
    __shared__ int s[1024];
    int t = threadIdx.x;
    s[t] = (t < NN) ? g_deg[t] : 0;
    __syncthreads();
    for (int d = 1; d < 1024; d <<= 1) {
        int v = (t >= d) ? s[t - d] : 0;
        __syncthreads();
        s[t] += v;
        __syncthreads();
    }
    if (t < NN) g_off[t + 1] = s[t];
    if (t == 0) g_off[0] = 0;
}

__global__ void k_scatter(const int* __restrict__ ei) {
    int i = blockIdx.x * blockDim.x + threadIdx.x;
    if (i >= EA) return;
    int s, d;
    if (i < EE) { s = ei[i]; d = ei[EE + i]; }
    else        { s = d = i - EE; }           // self loop
    int pos = atomicAdd(&g_cursor[d], 1);
    g_csr[g_off[d] + pos] = s;
}

// ---------------- node transform: xp = x @ W_gat ; a_s, a_d ----------------
__global__ void __launch_bounds__(256) k_transform(
    const float* __restrict__ x, const float* __restrict__ Wg,
    const float* __restrict__ att_s, const float* __restrict__ att_d)
{
    int w = blockIdx.x * 8 + (threadIdx.x >> 5);   // warp id = (g,n)
    int lane = threadIdx.x & 31;
    int g = w / NN, n = w % NN;

    float xv = 0.0f;
    if (lane < FIN) xv = x[(g * NN + n) * FIN + lane];

    float a0 = 0.f, a1 = 0.f, a2 = 0.f, a3 = 0.f;   // channels lane + 32h
#pragma unroll
    for (int f = 0; f < FIN; f++) {
        float xf = __shfl_sync(FULL, xv, f);
        const float* wr = Wg + f * HD + lane;
        a0 += xf * wr[0];
        a1 += xf * wr[32];
        a2 += xf * wr[64];
        a3 += xf * wr[96];
    }
    float* xr = g_xp + (size_t)(g * NN + n) * HD + lane;
    xr[0] = a0; xr[32] = a1; xr[64] = a2; xr[96] = a3;

    // a_s[h] = sum_d xp[h,d] * att_src[h,d]  (lane = d)
    float s0 = a0 * att_s[lane],      s1 = a1 * att_s[32 + lane];
    float s2 = a2 * att_s[64 + lane], s3 = a3 * att_s[96 + lane];
    float d0 = a0 * att_d[lane],      d1 = a1 * att_d[32 + lane];
    float d2 = a2 * att_d[64 + lane], d3 = a3 * att_d[96 + lane];
#pragma unroll
    for (int o = 16; o; o >>= 1) {
        s0 += __shfl_xor_sync(FULL, s0, o); s1 += __shfl_xor_sync(FULL, s1, o);
        s2 += __shfl_xor_sync(FULL, s2, o); s3 += __shfl_xor_sync(FULL, s3, o);
        d0 += __shfl_xor_sync(FULL, d0, o); d1 += __shfl_xor_sync(FULL, d1, o);
        d2 += __shfl_xor_sync(FULL, d2, o); d3 += __shfl_xor_sync(FULL, d3, o);
    }
    if (lane == 0) {
        float* ps = g_as + (size_t)(g * NN + n) * 4;
        ps[0] = s0; ps[1] = s1; ps[2] = s2; ps[3] = s3;
        float* pd = g_ad + (size_t)(g * NN + n) * 4;
        pd[0] = d0; pd[1] = d1; pd[2] = d2; pd[3] = d3;
    }
}

// ---------------- GAT softmax + aggregate + relu + max-pool ----------------
__device__ __forceinline__ float leaky02(float v) {
    return v >= 0.0f ? v : 0.2f * v;
}

__global__ void __launch_bounds__(256) k_gat(const float* __restrict__ bg)
{
    int w = blockIdx.x * 8 + (threadIdx.x >> 5);   // warp per (g,n) where n = dst
    int lane = threadIdx.x & 31;
    int g = w / NN, n = w % NN;

    int off0 = g_off[n];
    int cnt  = g_off[n + 1] - off0;                // >= 1 (self loop)

    const float4 adv = *(const float4*)(g_ad + (size_t)(g * NN + n) * 4);

    // pass 1: per-head max over incoming edges (lane-parallel)
    float m0 = -1e30f, m1 = -1e30f, m2 = -1e30f, m3 = -1e30f;
    for (int j = lane; j < cnt; j += 32) {
        int s = g_csr[off0 + j];
        float4 a = *(const float4*)(g_as + (size_t)(g * NN + s) * 4);
        m0 = fmaxf(m0, leaky02(a.x + adv.x));
        m1 = fmaxf(m1, leaky02(a.y + adv.y));
        m2 = fmaxf(m2, leaky02(a.z + adv.z));
        m3 = fmaxf(m3, leaky02(a.w + adv.w));
    }
#pragma unroll
    for (int o = 16; o; o >>= 1) {
        m0 = fmaxf(m0, __shfl_xor_sync(FULL, m0, o));
        m1 = fmaxf(m1, __shfl_xor_sync(FULL, m1, o));
        m2 = fmaxf(m2, __shfl_xor_sync(FULL, m2, o));
        m3 = fmaxf(m3, __shfl_xor_sync(FULL, m3, o));
    }

    // lanes 0-3 own heads 0-3 for the softmax weights
    float adsel = (lane == 0) ? adv.x : (lane == 1) ? adv.y : (lane == 2) ? adv.z : adv.w;
    float msel  = (lane == 0) ? m0    : (lane == 1) ? m1    : (lane == 2) ? m2    : m3;

    float acc0 = 0.f, acc1 = 0.f, acc2 = 0.f, acc3 = 0.f, den = 0.f;
    const float* xpg = g_xp + (size_t)g * NN * HD;

    for (int j = 0; j < cnt; j++) {
        int s = g_csr[off0 + j];                   // uniform broadcast load
        float ex = 0.0f;
        if (lane < 4) {
            float av = g_as[(size_t)(g * NN + s) * 4 + lane];
            float v  = leaky02(av + adsel);
            ex = expf(v - msel);
            den += ex;
        }
        float e0 = __shfl_sync(FULL, ex, 0);
        float e1 = __shfl_sync(FULL, ex, 1);
        float e2 = __shfl_sync(FULL, ex, 2);
        float e3 = __shfl_sync(FULL, ex, 3);
        const float* xr = xpg + (size_t)s * HD + lane;   // coalesced 4x128B
        acc0 += e0 * xr[0];
        acc1 += e1 * xr[32];
        acc2 += e2 * xr[64];
        acc3 += e3 * xr[96];
    }
    float dn0 = __shfl_sync(FULL, den, 0);
    float dn1 = __shfl_sync(FULL, den, 1);
    float dn2 = __shfl_sync(FULL, den, 2);
    float dn3 = __shfl_sync(FULL, den, 3);

    float o0 = fmaxf(acc0 / dn0 + bg[lane],      0.0f);
    float o1 = fmaxf(acc1 / dn1 + bg[32 + lane], 0.0f);
    float o2 = fmaxf(acc2 / dn2 + bg[64 + lane], 0.0f);
    float o3 = fmaxf(acc3 / dn3 + bg[96 + lane], 0.0f);

    int* pool = (int*)(g_pooled + (size_t)g * HD + lane);
    atomicMax(pool +  0, __float_as_int(o0));    // valid: values >= 0
    atomicMax(pool + 32, __float_as_int(o1));
    atomicMax(pool + 64, __float_as_int(o2));
    atomicMax(pool + 96, __float_as_int(o3));
}

// ---------------- LSTM (16 steps) + classifier ----------------
__device__ __forceinline__ float sigmoidf(float x) { return 1.0f / (1.0f + expf(-x)); }

__global__ void __launch_bounds__(256) k_lstm(
    const float* __restrict__ W_ih, const float* __restrict__ W_hh,
    const float* __restrict__ b_ih, const float* __restrict__ b_hh,
    const float* __restrict__ W_clf, const float* __restrict__ b_clf,
    float* __restrict__ out)
{
    int b = blockIdx.x;          // 8 blocks
    int tid = threadIdx.x;       // 256 = 4*HL gates
    __shared__ float sh[HL], sc[HL], sg[4 * HL], sx[HD];

    if (tid < HL) { sh[tid] = 0.f; sc[tid] = 0.f; }
    __syncthreads();

    const float* wi = W_ih + tid * HD;
    const float* wh = W_hh + tid * HL;
    float bias = b_ih[tid] + b_hh[tid];

    for (int t = 0; t < TT; t++) {
        if (tid < HD) sx[tid] = g_pooled[(size_t)(b * TT + t) * HD + tid];
        __syncthreads();
        float acc = bias;
#pragma unroll 8
        for (int k = 0; k < HD; k++) acc += sx[k] * wi[k];
#pragma unroll 8
        for (int k = 0; k < HL; k++) acc += sh[k] * wh[k];
        sg[tid] = acc;
        __syncthreads();
        if (tid < HL) {
            float ig = sigmoidf(sg[tid]);
            float fg = sigmoidf(sg[HL + tid]);
            float gg = tanhf(sg[2 * HL + tid]);
            float og = sigmoidf(sg[3 * HL + tid]);
            float cn = fg * sc[tid] + ig * gg;
            sc[tid] = cn;
            sh[tid] = og * tanhf(cn);
        }
        __syncthreads();
    }

    if (tid < NOUT) {
        float acc = b_clf[tid];
        const float* wc = W_clf + tid * HL;
#pragma unroll 8
        for (int k = 0; k < HL; k++) acc += sh[k] * wc[k];
        out[b * NOUT + tid] = acc;
    }
}

// ---------------- launch ----------------
extern "C" void kernel_launch(void* const* d_in, const int* in_sizes, int n_in,
                              void* d_out, int out_size)
{
    const float* x      = (const float*)d_in[0];
    const int*   ei     = (const int*)  d_in[1];
    const float* W_gat  = (const float*)d_in[2];
    const float* att_s  = (const float*)d_in[3];
    const float* att_d  = (const float*)d_in[4];
    const float* b_gat  = (const float*)d_in[5];
    const float* W_ih   = (const float*)d_in[6];
    const float* W_hh   = (const float*)d_in[7];
    const float* b_ih   = (const float*)d_in[8];
    const float* b_hh   = (const float*)d_in[9];
    const float* W_clf  = (const float*)d_in[10];
    const float* b_clf  = (const float*)d_in[11];
    float* out = (float*)d_out;

    k_zero<<<(G * HD + 255) / 256, 256>>>();
    k_count<<<(EA + 255) / 256, 256>>>(ei);
    k_scan<<<1, 1024>>>();
    k_scatter<<<(EA + 255) / 256, 256>>>(ei);
    k_transform<<<(G * NN) / 8, 256>>>(x, W_gat, att_s, att_d);
    k_gat<<<(G * NN) / 8, 256>>>(b_gat);
    k_lstm<<<BB, 256>>>(W_ih, W_hh, b_ih, b_hh, b_clf ? W_clf : W_clf, b_clf, out);
}

// round 2
// speedup vs baseline: 1.0213x; 1.0213x over previous
#include <cuda_runtime.h>
#include <math.h>

#define G    128      // B*T graphs
#define NN   1000
#define FIN  16
#define HH   4
#define DD   32
#define HD   128
#define EE   16000
#define EA   17000    // + self loops
#define HL   64
#define TT   16
#define BB   8
#define NOUT 8

#define FULL 0xffffffffu

// ---- scratch (device globals; no allocations allowed) ----
__device__ float g_xp[G * NN * HD];     // 65.5 MB, mostly L2-resident
__device__ float g_as[G * NN * HH];
__device__ float g_ad[G * NN * HH];
__device__ float g_pooled[G * HD];
__device__ int   g_deg[NN];
__device__ int   g_off[NN + 1];
__device__ int   g_cursor[NN];
__device__ int   g_csr[EA];

// ---------------- CSR build ----------------
__global__ void k_zero() {
    int i = blockIdx.x * blockDim.x + threadIdx.x;
    if (i < NN) { g_deg[i] = 0; g_cursor[i] = 0; }
    if (i < G * HD) g_pooled[i] = 0.0f;   // relu output >= 0, so 0 is a safe max-identity
}

__global__ void k_count(const int* __restrict__ ei) {
    int i = blockIdx.x * blockDim.x + threadIdx.x;
    if (i >= EA) return;
    int d = (i < EE) ? ei[EE + i] : (i - EE);   // ei: [2,E] row-major; row1 = dst
    atomicAdd(&g_deg[d], 1);
}

__global__ void k_scan() {
    __shared__ int s[1024];
    int t = threadIdx.x;
    s[t] = (t < NN) ? g_deg[t] : 0;
    __syncthreads();
    for (int d = 1; d < 1024; d <<= 1) {
        int v = (t >= d) ? s[t - d] : 0;
        __syncthreads();
        s[t] += v;
        __syncthreads();
    }
    if (t < NN) g_off[t + 1] = s[t];
    if (t == 0) g_off[0] = 0;
}

__global__ void k_scatter(const int* __restrict__ ei) {
    int i = blockIdx.x * blockDim.x + threadIdx.x;
    if (i >= EA) return;
    int s, d;
    if (i < EE) { s = ei[i]; d = ei[EE + i]; }
    else        { s = d = i - EE; }           // self loop
    int pos = atomicAdd(&g_cursor[d], 1);
    g_csr[g_off[d] + pos] = s;
}

// ---------------- node transform: xp = x @ W_gat ; a_s, a_d ----------------
__global__ void __launch_bounds__(256) k_transform(
    const float* __restrict__ x, const float* __restrict__ Wg,
    const float* __restrict__ att_s, const float* __restrict__ att_d)
{
    int w = blockIdx.x * 8 + (threadIdx.x >> 5);   // warp id = (g,n)
    int lane = threadIdx.x & 31;
    int g = w / NN, n = w % NN;

    float xv = 0.0f;
    if (lane < FIN) xv = x[(g * NN + n) * FIN + lane];

    float a0 = 0.f, a1 = 0.f, a2 = 0.f, a3 = 0.f;   // channels lane + 32h
#pragma unroll
    for (int f = 0; f < FIN; f++) {
        float xf = __shfl_sync(FULL, xv, f);
        const float* wr = Wg + f * HD + lane;
        a0 += xf * wr[0];
        a1 += xf * wr[32];
        a2 += xf * wr[64];
        a3 += xf * wr[96];
    }
    float* xr = g_xp + (size_t)(g * NN + n) * HD + lane;
    xr[0] = a0; xr[32] = a1; xr[64] = a2; xr[96] = a3;

    // a_s[h] = sum_d xp[h,d] * att_src[h,d]  (lane = d)
    float s0 = a0 * att_s[lane],      s1 = a1 * att_s[32 + lane];
    float s2 = a2 * att_s[64 + lane], s3 = a3 * att_s[96 + lane];
    float d0 = a0 * att_d[lane],      d1 = a1 * att_d[32 + lane];
    float d2 = a2 * att_d[64 + lane], d3 = a3 * att_d[96 + lane];
#pragma unroll
    for (int o = 16; o; o >>= 1) {
        s0 += __shfl_xor_sync(FULL, s0, o); s1 += __shfl_xor_sync(FULL, s1, o);
        s2 += __shfl_xor_sync(FULL, s2, o); s3 += __shfl_xor_sync(FULL, s3, o);
        d0 += __shfl_xor_sync(FULL, d0, o); d1 += __shfl_xor_sync(FULL, d1, o);
        d2 += __shfl_xor_sync(FULL, d2, o); d3 += __shfl_xor_sync(FULL, d3, o);
    }
    if (lane == 0) {
        float* ps = g_as + (size_t)(g * NN + n) * 4;
        ps[0] = s0; ps[1] = s1; ps[2] = s2; ps[3] = s3;
        float* pd = g_ad + (size_t)(g * NN + n) * 4;
        pd[0] = d0; pd[1] = d1; pd[2] = d2; pd[3] = d3;
    }
}

// ---------------- GAT softmax (no max-shift) + aggregate + relu + max-pool --
__global__ void __launch_bounds__(256) k_gat(const float* __restrict__ bg)
{
    int w = blockIdx.x * 8 + (threadIdx.x >> 5);   // warp per (g,n), n = dst
    int lane = threadIdx.x & 31;
    int g = w / NN, n = w % NN;

    int off0 = g_off[n];
    int cnt  = g_off[n + 1] - off0;                // >= 1 (self loop)

    int h  = lane & 3;                             // head owned for score calc
    int jj = lane >> 2;                            // edge-within-chunk owned

    float adh = g_ad[(size_t)(g * NN + n) * 4 + h];

    float acc0 = 0.f, acc1 = 0.f, acc2 = 0.f, acc3 = 0.f, den = 0.f;
    const float* xpg = g_xp + (size_t)g * NN * HD;

    for (int base = 0; base < cnt; base += 8) {
        int rem = cnt - base;                      // uniform across warp
        int s_l = 0;
        if (lane < 8 && lane < rem) s_l = g_csr[off0 + base + lane];

        // all 32 lanes: exp score for (edge jj, head h) of this chunk
        int   sj = __shfl_sync(FULL, s_l, jj);
        float ex = 0.f;
        if (jj < rem) {
            float v = g_as[(size_t)(g * NN + sj) * 4 + h] + adh;
            v = (v >= 0.f) ? v : 0.2f * v;         // leaky relu 0.2
            ex = expf(v);                          // safe: |v| <~ 8
            den += ex;
        }

        // accumulate: 8 independent gather chains -> high MLP
#pragma unroll
        for (int q = 0; q < 8; q++) {
            if (q < rem) {
                int   s  = __shfl_sync(FULL, s_l, q);
                float e0 = __shfl_sync(FULL, ex, 4 * q + 0);
                float e1 = __shfl_sync(FULL, ex, 4 * q + 1);
                float e2 = __shfl_sync(FULL, ex, 4 * q + 2);
                float e3 = __shfl_sync(FULL, ex, 4 * q + 3);
                const float* xr = xpg + (size_t)s * HD + lane;
                acc0 += e0 * xr[0];
                acc1 += e1 * xr[32];
                acc2 += e2 * xr[64];
                acc3 += e3 * xr[96];
            }
        }
    }

    // reduce den across lanes sharing the same head (stride-4 groups)
#pragma unroll
    for (int o = 16; o >= 4; o >>= 1) den += __shfl_xor_sync(FULL, den, o);
    float dn0 = __shfl_sync(FULL, den, 0);
    float dn1 = __shfl_sync(FULL, den, 1);
    float dn2 = __shfl_sync(FULL, den, 2);
    float dn3 = __shfl_sync(FULL, den, 3);

    float o0 = fmaxf(acc0 / dn0 + bg[lane],      0.0f);
    float o1 = fmaxf(acc1 / dn1 + bg[32 + lane], 0.0f);
    float o2 = fmaxf(acc2 / dn2 + bg[64 + lane], 0.0f);
    float o3 = fmaxf(acc3 / dn3 + bg[96 + lane], 0.0f);

    int* pool = (int*)(g_pooled + (size_t)g * HD + lane);
    atomicMax(pool +  0, __float_as_int(o0));    // valid: values >= 0
    atomicMax(pool + 32, __float_as_int(o1));
    atomicMax(pool + 64, __float_as_int(o2));
    atomicMax(pool + 96, __float_as_int(o3));
}

// ---------------- LSTM (16 steps) + classifier ----------------
__device__ __forceinline__ float sigmoidf(float x) { return 1.0f / (1.0f + expf(-x)); }

__global__ void __launch_bounds__(256) k_lstm(
    const float* __restrict__ W_ih, const float* __restrict__ W_hh,
    const float* __restrict__ b_ih, const float* __restrict__ b_hh,
    const float* __restrict__ W_clf, const float* __restrict__ b_clf,
    float* __restrict__ out)
{
    int b = blockIdx.x;          // 8 blocks
    int tid = threadIdx.x;       // 256 = 4*HL gates
    __shared__ float sh[HL], sc[HL], sg[4 * HL], sx[HD];

    if (tid < HL) { sh[tid] = 0.f; sc[tid] = 0.f; }
    __syncthreads();

    const float* wi = W_ih + tid * HD;
    const float* wh = W_hh + tid * HL;
    float bias = b_ih[tid] + b_hh[tid];

    for (int t = 0; t < TT; t++) {
        if (tid < HD) sx[tid] = g_pooled[(size_t)(b * TT + t) * HD + tid];
        __syncthreads();
        float acc = bias;
#pragma unroll 8
        for (int k = 0; k < HD; k++) acc += sx[k] * wi[k];
#pragma unroll 8
        for (int k = 0; k < HL; k++) acc += sh[k] * wh[k];
        sg[tid] = acc;
        __syncthreads();
        if (tid < HL) {
            float ig = sigmoidf(sg[tid]);
            float fg = sigmoidf(sg[HL + tid]);
            float gg = tanhf(sg[2 * HL + tid]);
            float og = sigmoidf(sg[3 * HL + tid]);
            float cn = fg * sc[tid] + ig * gg;
            sc[tid] = cn;
            sh[tid] = og * tanhf(cn);
        }
        __syncthreads();
    }

    if (tid < NOUT) {
        float acc = b_clf[tid];
        const float* wc = W_clf + tid * HL;
#pragma unroll 8
        for (int k = 0; k < HL; k++) acc += sh[k] * wc[k];
        out[b * NOUT + tid] = acc;
    }
}

// ---------------- launch ----------------
extern "C" void kernel_launch(void* const* d_in, const int* in_sizes, int n_in,
                              void* d_out, int out_size)
{
    const float* x      = (const float*)d_in[0];
    const int*   ei     = (const int*)  d_in[1];
    const float* W_gat  = (const float*)d_in[2];
    const float* att_s  = (const float*)d_in[3];
    const float* att_d  = (const float*)d_in[4];
    const float* b_gat  = (const float*)d_in[5];
    const float* W_ih   = (const float*)d_in[6];
    const float* W_hh   = (const float*)d_in[7];
    const float* b_ih   = (const float*)d_in[8];
    const float* b_hh   = (const float*)d_in[9];
    const float* W_clf  = (const float*)d_in[10];
    const float* b_clf  = (const float*)d_in[11];
    float* out = (float*)d_out;

    k_zero<<<(G * HD + 255) / 256, 256>>>();
    k_count<<<(EA + 255) / 256, 256>>>(ei);
    k_scan<<<1, 1024>>>();
    k_scatter<<<(EA + 255) / 256, 256>>>(ei);
    k_transform<<<(G * NN) / 8, 256>>>(x, W_gat, att_s, att_d);
    k_gat<<<(G * NN) / 8, 256>>>(b_gat);
    k_lstm<<<BB, 256>>>(W_ih, W_hh, b_ih, b_hh, W_clf, b_clf, out);
}